// round 1
// baseline (speedup 1.0000x reference)
#include <cuda_runtime.h>
#include <math.h>

#define Bc   64
#define Nc   1000
#define Dc   128
#define Ec   20000
#define BNc  64000

// ---------------- scratch (static device globals; no allocation) -------------
__device__ float g_x[BNc * Dc];      // X @ lin_w^T
__device__ float g_u[BNc * Dc];      // X @ W1b_eff^T (folded temporal branch)
__device__ float g_agg[BNc * Dc];    // graph aggregation output
__device__ float g_ni[BNc];
__device__ float g_nj[BNc];
__device__ float g_esi[Nc];
__device__ float g_esj[Nc];
__device__ float g_W1b[Dc * Dc];     // f_w1[:,128:] @ v_w
__device__ float g_b1e[Dc];
__device__ float g_cvec[Dc];         // f_w2^T @ out_w^T
__device__ float g_b0;
__device__ int   g_deg[Nc];
__device__ int   g_rowptr[Nc + 1];
__device__ int   g_csr[Ec];
__device__ float g_bnsum[Dc];
__device__ float g_bnsq[Dc];
__device__ float g_scale[Dc];
__device__ float g_shift[Dc];

// ---------------- tiny prep kernels ------------------------------------------
__global__ void k_misc(const float* __restrict__ f_w1, const float* __restrict__ f_b1,
                       const float* __restrict__ f_w2, const float* __restrict__ f_b2,
                       const float* __restrict__ v_b,  const float* __restrict__ out_w,
                       const float* __restrict__ out_b) {
    int t = threadIdx.x;
    if (t < Dc) {
        float acc = 0.f, cv = 0.f;
        for (int d = 0; d < Dc; d++) {
            acc += f_w1[t * 2 * Dc + Dc + d] * v_b[d];
            cv  += out_w[d] * f_w2[d * Dc + t];
        }
        g_b1e[t]  = f_b1[t] + acc;
        g_cvec[t] = cv;
        g_bnsum[t] = 0.f;
        g_bnsq[t]  = 0.f;
    }
    if (t == 0) {
        float b0 = out_b[0];
        for (int d = 0; d < Dc; d++) b0 += out_w[d] * f_b2[d];
        g_b0 = b0;
    }
    for (int i = t; i < Nc; i += blockDim.x) g_deg[i] = 0;
}

// W1b_eff[ko][c] = sum_d f_w1[ko][128+d] * v_w[d][c]
__global__ void k_w1b(const float* __restrict__ f_w1, const float* __restrict__ v_w) {
    int ko = blockIdx.x, c = threadIdx.x;
    const float* row = f_w1 + ko * 2 * Dc + Dc;
    float acc = 0.f;
#pragma unroll 8
    for (int d = 0; d < Dc; d++) acc += row[d] * v_w[d * Dc + c];
    g_W1b[ko * Dc + c] = acc;
}

// per-graph-node embedding scores (warp per row)
__global__ void k_emb(const float* __restrict__ emb, const float* __restrict__ aei,
                      const float* __restrict__ aej) {
    int w = blockIdx.x * 8 + (threadIdx.x >> 5);
    int l = threadIdx.x & 31;
    if (w >= Nc) return;
    float4 ev = ((const float4*)(emb + w * Dc))[l];
    float4 ai = ((const float4*)aei)[l];
    float4 aj = ((const float4*)aej)[l];
    float si = ev.x * ai.x + ev.y * ai.y + ev.z * ai.z + ev.w * ai.w;
    float sj = ev.x * aj.x + ev.y * aj.y + ev.z * aj.z + ev.w * aj.w;
#pragma unroll
    for (int o = 16; o; o >>= 1) {
        si += __shfl_xor_sync(0xFFFFFFFFu, si, o);
        sj += __shfl_xor_sync(0xFFFFFFFFu, sj, o);
    }
    if (!l) { g_esi[w] = si; g_esj[w] = sj; }
}

__global__ void k_deg(const int* __restrict__ ei) {
    int e = blockIdx.x * blockDim.x + threadIdx.x;
    if (e < Ec) atomicAdd(&g_deg[ei[Ec + e]], 1);
}

__global__ void k_scan() {
    __shared__ int sd[1024];
    int t = threadIdx.x;
    sd[t] = (t < Nc) ? g_deg[t] : 0;
    __syncthreads();
    for (int off = 1; off < 1024; off <<= 1) {
        int tmp = (t >= off) ? sd[t - off] : 0;
        __syncthreads();
        sd[t] += tmp;
        __syncthreads();
    }
    if (t == 0) g_rowptr[0] = 0;
    if (t < Nc) g_rowptr[t + 1] = sd[t];
}

// deterministic CSR fill: thread per dst scans all edges (edges cached in L1/L2)
__global__ void k_fill(const int* __restrict__ ei) {
    int d = blockIdx.x * blockDim.x + threadIdx.x;
    if (d >= Nc) return;
    int p = g_rowptr[d];
    for (int e = 0; e < Ec; e++) {
        if (__ldg(&ei[Ec + e]) == d) g_csr[p++] = __ldg(&ei[e]);
    }
}

// ---------------- GEMM 1: x = X@lin_w^T, u = X@W1b_eff^T ---------------------
// block: 64 rows x 256 cols, K=128 in one shot. As[128][65], Bs[128][257].
__global__ __launch_bounds__(256) void k_gemm1(const float* __restrict__ data,
                                               const float* __restrict__ lin_w) {
    extern __shared__ float sm[];
    float* As = sm;             // [128][65]  (k-major, padded)
    float* Bs = sm + 128 * 65;  // [128][257] (k-major, padded; cols 0..127 = x, 128..255 = u)
    int tid = threadIdx.x;
    int row0 = blockIdx.x * 64;

    for (int idx = tid; idx < 64 * 128; idx += 256) {
        int m = idx >> 7, k = idx & 127;
        As[k * 65 + m] = data[(row0 + m) * Dc + k];
    }
    for (int idx = tid; idx < 128 * 128; idx += 256) {
        int n = idx >> 7, k = idx & 127;
        Bs[k * 257 + n]       = lin_w[n * Dc + k];
        Bs[k * 257 + 128 + n] = g_W1b[n * Dc + k];
    }
    __syncthreads();

    int ty = tid >> 5, lane = tid & 31;
    int rb = ty * 8;
    float acc[8][8];
#pragma unroll
    for (int i = 0; i < 8; i++)
#pragma unroll
        for (int j = 0; j < 8; j++) acc[i][j] = 0.f;

#pragma unroll 4
    for (int k = 0; k < 128; k++) {
        float a[8], b[8];
#pragma unroll
        for (int i = 0; i < 8; i++) a[i] = As[k * 65 + rb + i];
#pragma unroll
        for (int j = 0; j < 8; j++) b[j] = Bs[k * 257 + lane + 32 * j];
#pragma unroll
        for (int i = 0; i < 8; i++)
#pragma unroll
            for (int j = 0; j < 8; j++) acc[i][j] += a[i] * b[j];
    }

#pragma unroll
    for (int i = 0; i < 8; i++) {
        int row = row0 + rb + i;
#pragma unroll
        for (int j = 0; j < 4; j++) g_x[row * Dc + lane + 32 * j] = acc[i][j];
#pragma unroll
        for (int j = 4; j < 8; j++) g_u[row * Dc + lane + 32 * (j - 4)] = acc[i][j];
    }
}

// ni/nj per row (warp per row)
__global__ void k_scores(const float* __restrict__ att_i, const float* __restrict__ att_j) {
    int w = blockIdx.x * 8 + (threadIdx.x >> 5);
    int l = threadIdx.x & 31;
    float4 xv = ((const float4*)(g_x + (size_t)w * Dc))[l];
    float4 ai = ((const float4*)att_i)[l];
    float4 aj = ((const float4*)att_j)[l];
    float si = xv.x * ai.x + xv.y * ai.y + xv.z * ai.z + xv.w * ai.w;
    float sj = xv.x * aj.x + xv.y * aj.y + xv.z * aj.z + xv.w * aj.w;
#pragma unroll
    for (int o = 16; o; o >>= 1) {
        si += __shfl_xor_sync(0xFFFFFFFFu, si, o);
        sj += __shfl_xor_sync(0xFFFFFFFFu, sj, o);
    }
    if (!l) {
        int n = w % Nc;
        g_ni[w] = si + g_esi[n];
        g_nj[w] = sj + g_esj[n];
    }
}

// ---------------- graph attention aggregation (warp per node) ----------------
__global__ __launch_bounds__(256) void k_agg(const float* __restrict__ gnn_bias) {
    __shared__ float ss[128], sq[128];
    int tid = threadIdx.x;
    if (tid < 128) { ss[tid] = 0.f; sq[tid] = 0.f; }
    __syncthreads();

    int w = blockIdx.x * 8 + (tid >> 5);
    int l = tid & 31;
    int b = w / Nc;
    int i = w - b * Nc;
    int base = b * Nc;

    float nir = g_ni[w];
    float sa = nir + g_nj[w];
    sa = sa >= 0.f ? sa : 0.2f * sa;          // self-loop alpha (leaky relu)
    float m = sa;
    int s0 = g_rowptr[i], s1 = g_rowptr[i + 1];
    for (int e = s0; e < s1; e++) {
        int s = g_csr[e];
        float a = nir + g_nj[base + s];
        a = a >= 0.f ? a : 0.2f * a;
        m = fmaxf(m, a);
    }
    float exs = expf(sa - m);
    float den = exs;
    float4 xv = ((const float4*)(g_x + (size_t)w * Dc))[l];
    float4 acc;
    acc.x = xv.x * exs; acc.y = xv.y * exs; acc.z = xv.z * exs; acc.w = xv.w * exs;

    for (int e = s0; e < s1; e++) {
        int s = g_csr[e];
        float a = nir + g_nj[base + s];
        a = a >= 0.f ? a : 0.2f * a;
        float ex = expf(a - m);
        den += ex;
        float4 v = ((const float4*)(g_x + (size_t)(base + s) * Dc))[l];
        acc.x += v.x * ex; acc.y += v.y * ex; acc.z += v.z * ex; acc.w += v.w * ex;
    }
    float inv = 1.f / den;
    float4 bias = ((const float4*)gnn_bias)[l];
    float4 agg;
    agg.x = acc.x * inv + bias.x;
    agg.y = acc.y * inv + bias.y;
    agg.z = acc.z * inv + bias.z;
    agg.w = acc.w * inv + bias.w;
    ((float4*)(g_agg + (size_t)w * Dc))[l] = agg;

    atomicAdd(&ss[l * 4 + 0], agg.x);  atomicAdd(&sq[l * 4 + 0], agg.x * agg.x);
    atomicAdd(&ss[l * 4 + 1], agg.y);  atomicAdd(&sq[l * 4 + 1], agg.y * agg.y);
    atomicAdd(&ss[l * 4 + 2], agg.z);  atomicAdd(&sq[l * 4 + 2], agg.z * agg.z);
    atomicAdd(&ss[l * 4 + 3], agg.w);  atomicAdd(&sq[l * 4 + 3], agg.w * agg.w);
    __syncthreads();
    if (tid < 128) atomicAdd(&g_bnsum[tid], ss[tid]);
    else           atomicAdd(&g_bnsq[tid - 128], sq[tid - 128]);
}

__global__ void k_bnfin(const float* __restrict__ gamma, const float* __restrict__ beta) {
    int t = threadIdx.x;
    float mu = g_bnsum[t] / (float)BNc;
    float var = g_bnsq[t] / (float)BNc - mu * mu;
    float rstd = rsqrtf(var + 1e-5f);
    float sc = gamma[t] * rstd;
    g_scale[t] = sc;
    g_shift[t] = beta[t] - mu * sc;
}

// ---------------- GEMM 2 + epilogue: out = relu(s@W1a^T + u + b1e) . cvec ----
__global__ __launch_bounds__(256) void k_gemm2(const float* __restrict__ f_w1,
                                               float* __restrict__ out) {
    extern __shared__ float sm[];
    float* As = sm;             // [128][65]  s tile (BN+relu applied on load)
    float* Bs = sm + 128 * 65;  // [128][129] W1a transposed
    int tid = threadIdx.x;
    int row0 = blockIdx.x * 64;

    for (int idx = tid; idx < 64 * 128; idx += 256) {
        int m = idx >> 7, j = idx & 127;
        float v = g_agg[(size_t)(row0 + m) * Dc + j];
        float s = v * g_scale[j] + g_shift[j];
        As[j * 65 + m] = s > 0.f ? s : 0.f;
    }
    for (int idx = tid; idx < 128 * 128; idx += 256) {
        int ko = idx >> 7, j = idx & 127;
        Bs[j * 129 + ko] = f_w1[ko * 2 * Dc + j];
    }
    __syncthreads();

    int ty = tid >> 5, lane = tid & 31;
    int rb = ty * 8;
    float acc[8][4];
#pragma unroll
    for (int i = 0; i < 8; i++)
#pragma unroll
        for (int j = 0; j < 4; j++) acc[i][j] = 0.f;

    float cv[4], b1r[4];
#pragma unroll
    for (int jj = 0; jj < 4; jj++) {
        int col = lane + 32 * jj;
        cv[jj] = g_cvec[col];
        b1r[jj] = g_b1e[col];
    }

#pragma unroll 4
    for (int k = 0; k < 128; k++) {
        float a[8], bv[4];
#pragma unroll
        for (int i = 0; i < 8; i++) a[i] = As[k * 65 + rb + i];
#pragma unroll
        for (int jj = 0; jj < 4; jj++) bv[jj] = Bs[k * 129 + lane + 32 * jj];
#pragma unroll
        for (int i = 0; i < 8; i++)
#pragma unroll
            for (int jj = 0; jj < 4; jj++) acc[i][jj] += a[i] * bv[jj];
    }

    float b0 = g_b0;
#pragma unroll
    for (int i = 0; i < 8; i++) {
        int row = row0 + rb + i;
        float part = 0.f;
#pragma unroll
        for (int jj = 0; jj < 4; jj++) {
            int col = lane + 32 * jj;
            float h = acc[i][jj] + g_u[(size_t)row * Dc + col] + b1r[jj];
            h = h > 0.f ? h : 0.f;
            part += h * cv[jj];
        }
#pragma unroll
        for (int o = 16; o; o >>= 1) part += __shfl_xor_sync(0xFFFFFFFFu, part, o);
        if (!lane) out[row] = part + b0;
    }
}

// ---------------- launch ------------------------------------------------------
extern "C" void kernel_launch(void* const* d_in, const int* in_sizes, int n_in,
                              void* d_out, int out_size) {
    const float* data    = (const float*)d_in[0];
    const int*   ei      = (const int*)d_in[1];
    const float* emb     = (const float*)d_in[2];
    const float* lin_w   = (const float*)d_in[3];
    const float* att_i   = (const float*)d_in[4];
    const float* att_j   = (const float*)d_in[5];
    const float* aei     = (const float*)d_in[6];
    const float* aej     = (const float*)d_in[7];
    const float* gnn_b   = (const float*)d_in[8];
    const float* gamma   = (const float*)d_in[9];
    const float* beta    = (const float*)d_in[10];
    const float* v_w     = (const float*)d_in[15];
    const float* v_b     = (const float*)d_in[16];
    const float* f_w1    = (const float*)d_in[18];
    const float* f_b1    = (const float*)d_in[19];
    const float* f_w2    = (const float*)d_in[20];
    const float* f_b2    = (const float*)d_in[21];
    const float* out_w   = (const float*)d_in[22];
    const float* out_b   = (const float*)d_in[23];
    float* out = (float*)d_out;

    size_t sm1 = (size_t)(128 * 65 + 128 * 257) * 4;
    size_t sm2 = (size_t)(128 * 65 + 128 * 129) * 4;
    cudaFuncSetAttribute(k_gemm1, cudaFuncAttributeMaxDynamicSharedMemorySize, (int)sm1);
    cudaFuncSetAttribute(k_gemm2, cudaFuncAttributeMaxDynamicSharedMemorySize, (int)sm2);

    k_misc<<<1, 256>>>(f_w1, f_b1, f_w2, f_b2, v_b, out_w, out_b);
    k_w1b<<<128, 128>>>(f_w1, v_w);
    k_emb<<<125, 256>>>(emb, aei, aej);
    k_deg<<<40, 512>>>(ei);
    k_scan<<<1, 1024>>>();
    k_fill<<<2, 512>>>(ei);
    k_gemm1<<<1000, 256, sm1>>>(data, lin_w);
    k_scores<<<8000, 256>>>(att_i, att_j);
    k_agg<<<8000, 256>>>(gnn_b);
    k_bnfin<<<1, 128>>>(gamma, beta);
    k_gemm2<<<1000, 256, sm2>>>(f_w1, out);
}

// round 2
// speedup vs baseline: 2.8376x; 2.8376x over previous
#include <cuda_runtime.h>
#include <math.h>

#define Bc   64
#define Nc   1000
#define Dc   128
#define Ec   20000
#define BNc  64000

// ---------------- scratch (static device globals; no allocation) -------------
__device__ float g_x[BNc * Dc];      // X @ lin_w^T
__device__ float g_u[BNc * Dc];      // X @ W1b_eff^T (folded temporal branch)
__device__ float g_agg[BNc * Dc];    // graph aggregation output
__device__ float g_ni[BNc];
__device__ float g_nj[BNc];
__device__ float g_esi[Nc];
__device__ float g_esj[Nc];
__device__ float g_W1b[Dc * Dc];     // f_w1[:,128:] @ v_w
__device__ float g_b1e[Dc];
__device__ float g_cvec[Dc];         // f_w2^T @ out_w^T
__device__ float g_b0;
__device__ int   g_deg[Nc];
__device__ int   g_rowptr[Nc + 1];
__device__ int   g_cur[Nc];
__device__ int   g_csr[Ec];
__device__ float g_bnsum[Dc];
__device__ float g_bnsq[Dc];
__device__ float g_scale[Dc];
__device__ float g_shift[Dc];

// ---------------- tiny prep kernels ------------------------------------------
__global__ void k_misc(const float* __restrict__ f_w1, const float* __restrict__ f_b1,
                       const float* __restrict__ f_w2, const float* __restrict__ f_b2,
                       const float* __restrict__ v_b,  const float* __restrict__ out_w,
                       const float* __restrict__ out_b) {
    int t = threadIdx.x;
    if (t < Dc) {
        float acc = 0.f, cv = 0.f;
        for (int d = 0; d < Dc; d++) {
            acc += f_w1[t * 2 * Dc + Dc + d] * v_b[d];
            cv  += out_w[d] * f_w2[d * Dc + t];
        }
        g_b1e[t]  = f_b1[t] + acc;
        g_cvec[t] = cv;
        g_bnsum[t] = 0.f;
        g_bnsq[t]  = 0.f;
    }
    if (t == 0) {
        float b0 = out_b[0];
        for (int d = 0; d < Dc; d++) b0 += out_w[d] * f_b2[d];
        g_b0 = b0;
    }
    for (int i = t; i < Nc; i += blockDim.x) g_deg[i] = 0;
}

// W1b_eff[ko][c] = sum_d f_w1[ko][128+d] * v_w[d][c]
__global__ void k_w1b(const float* __restrict__ f_w1, const float* __restrict__ v_w) {
    int ko = blockIdx.x, c = threadIdx.x;
    const float* row = f_w1 + ko * 2 * Dc + Dc;
    float acc = 0.f;
#pragma unroll 8
    for (int d = 0; d < Dc; d++) acc += row[d] * v_w[d * Dc + c];
    g_W1b[ko * Dc + c] = acc;
}

// per-graph-node embedding scores (warp per row)
__global__ void k_emb(const float* __restrict__ emb, const float* __restrict__ aei,
                      const float* __restrict__ aej) {
    int w = blockIdx.x * 8 + (threadIdx.x >> 5);
    int l = threadIdx.x & 31;
    if (w >= Nc) return;
    float4 ev = ((const float4*)(emb + w * Dc))[l];
    float4 ai = ((const float4*)aei)[l];
    float4 aj = ((const float4*)aej)[l];
    float si = ev.x * ai.x + ev.y * ai.y + ev.z * ai.z + ev.w * ai.w;
    float sj = ev.x * aj.x + ev.y * aj.y + ev.z * aj.z + ev.w * aj.w;
#pragma unroll
    for (int o = 16; o; o >>= 1) {
        si += __shfl_xor_sync(0xFFFFFFFFu, si, o);
        sj += __shfl_xor_sync(0xFFFFFFFFu, sj, o);
    }
    if (!l) { g_esi[w] = si; g_esj[w] = sj; }
}

__global__ void k_deg(const int* __restrict__ ei) {
    int e = blockIdx.x * blockDim.x + threadIdx.x;
    if (e < Ec) atomicAdd(&g_deg[ei[Ec + e]], 1);
}

__global__ void k_scan() {
    __shared__ int sd[1024];
    int t = threadIdx.x;
    int d0 = (t < Nc) ? g_deg[t] : 0;
    sd[t] = d0;
    __syncthreads();
    for (int off = 1; off < 1024; off <<= 1) {
        int tmp = (t >= off) ? sd[t - off] : 0;
        __syncthreads();
        sd[t] += tmp;
        __syncthreads();
    }
    if (t == 0) g_rowptr[0] = 0;
    if (t < Nc) { g_rowptr[t + 1] = sd[t]; g_cur[t] = sd[t] - d0; }
}

// CSR fill via atomic cursors: one thread per edge (order within a row is
// atomic-ordered; only permutes fp summation order, ~1e-7 jitter)
__global__ void k_fill2(const int* __restrict__ ei) {
    int e = blockIdx.x * blockDim.x + threadIdx.x;
    if (e >= Ec) return;
    int d = ei[Ec + e];
    int p = atomicAdd(&g_cur[d], 1);
    g_csr[p] = ei[e];
}

// ---------------- GEMM 1: x = X@lin_w^T, u = X@W1b_eff^T, + attention scores -
// 64 rows/block, B processed in two 128-col halves -> 99KB smem -> 2 blocks/SM
__global__ __launch_bounds__(256) void k_gemm1(const float* __restrict__ data,
                                               const float* __restrict__ lin_w,
                                               const float* __restrict__ att_i,
                                               const float* __restrict__ att_j) {
    extern __shared__ float sm[];
    float* As = sm;             // [128][65]  k-major
    float* Bs = sm + 128 * 65;  // [128][129] k-major
    int tid = threadIdx.x;
    int row0 = blockIdx.x * 64;

    for (int idx = tid; idx < 64 * 128; idx += 256) {
        int m = idx >> 7, k = idx & 127;
        As[k * 65 + m] = data[(row0 + m) * Dc + k];
    }

    int ty = tid >> 5, lane = tid & 31;
    int rb = ty * 8;
    float xk[8][4];

    for (int cg = 0; cg < 2; cg++) {
        const float* Bsrc = cg ? g_W1b : lin_w;
        __syncthreads();   // cg=0: covers As load; cg=1: protects Bs overwrite
        for (int idx = tid; idx < 128 * 128; idx += 256) {
            int n = idx >> 7, k = idx & 127;
            Bs[k * 129 + n] = Bsrc[n * Dc + k];
        }
        __syncthreads();

        float acc[8][4];
#pragma unroll
        for (int i = 0; i < 8; i++)
#pragma unroll
            for (int j = 0; j < 4; j++) acc[i][j] = 0.f;

#pragma unroll 4
        for (int k = 0; k < 128; k++) {
            float a[8], b[4];
#pragma unroll
            for (int i = 0; i < 8; i++) a[i] = As[k * 65 + rb + i];
#pragma unroll
            for (int j = 0; j < 4; j++) b[j] = Bs[k * 129 + lane + 32 * j];
#pragma unroll
            for (int i = 0; i < 8; i++)
#pragma unroll
                for (int j = 0; j < 4; j++) acc[i][j] += a[i] * b[j];
        }

        float* dst = cg ? g_u : g_x;
#pragma unroll
        for (int i = 0; i < 8; i++)
#pragma unroll
            for (int j = 0; j < 4; j++)
                dst[(size_t)(row0 + rb + i) * Dc + lane + 32 * j] = acc[i][j];
        if (!cg) {
#pragma unroll
            for (int i = 0; i < 8; i++)
#pragma unroll
                for (int j = 0; j < 4; j++) xk[i][j] = acc[i][j];
        }
    }

    // fused attention scores: ni/nj per row from the x tile in registers
    float ai[4], aj[4];
#pragma unroll
    for (int j = 0; j < 4; j++) {
        ai[j] = att_i[lane + 32 * j];
        aj[j] = att_j[lane + 32 * j];
    }
#pragma unroll
    for (int i = 0; i < 8; i++) {
        float si = xk[i][0] * ai[0] + xk[i][1] * ai[1] + xk[i][2] * ai[2] + xk[i][3] * ai[3];
        float sj = xk[i][0] * aj[0] + xk[i][1] * aj[1] + xk[i][2] * aj[2] + xk[i][3] * aj[3];
#pragma unroll
        for (int o = 16; o; o >>= 1) {
            si += __shfl_xor_sync(0xFFFFFFFFu, si, o);
            sj += __shfl_xor_sync(0xFFFFFFFFu, sj, o);
        }
        if (!lane) {
            int row = row0 + rb + i;
            int n = row % Nc;
            g_ni[row] = si + g_esi[n];
            g_nj[row] = sj + g_esj[n];
        }
    }
}

// ---------------- graph attention aggregation --------------------------------
// 1000 blocks x 256 threads; each warp loops 8 nodes. Lane-parallel max/denom.
__global__ __launch_bounds__(256) void k_agg(const float* __restrict__ gnn_bias) {
    __shared__ float ss[128], sq[128];
    int tid = threadIdx.x;
    if (tid < 128) { ss[tid] = 0.f; sq[tid] = 0.f; }
    __syncthreads();

    int warp = tid >> 5, l = tid & 31;
    float4 bias = ((const float4*)gnn_bias)[l];
    float ls0 = 0.f, ls1 = 0.f, ls2 = 0.f, ls3 = 0.f;
    float lq0 = 0.f, lq1 = 0.f, lq2 = 0.f, lq3 = 0.f;

    for (int it = 0; it < 8; it++) {
        int w = blockIdx.x * 64 + it * 8 + warp;
        int b = w / Nc;
        int i = w - b * Nc;
        int base = b * Nc;

        float nir = g_ni[w];
        float sa = nir + g_nj[w];
        sa = sa >= 0.f ? sa : 0.2f * sa;
        int s0 = g_rowptr[i], s1 = g_rowptr[i + 1];

        // lane-parallel max
        float m = sa;
        for (int e = s0 + l; e < s1; e += 32) {
            int s = __ldg(&g_csr[e]);
            float a = nir + g_nj[base + s];
            a = a >= 0.f ? a : 0.2f * a;
            m = fmaxf(m, a);
        }
#pragma unroll
        for (int o = 16; o; o >>= 1) m = fmaxf(m, __shfl_xor_sync(0xFFFFFFFFu, m, o));

        // lane-parallel denominator
        float dp = (l == 0) ? expf(sa - m) : 0.f;
        for (int e = s0 + l; e < s1; e += 32) {
            int s = __ldg(&g_csr[e]);
            float a = nir + g_nj[base + s];
            a = a >= 0.f ? a : 0.2f * a;
            dp += expf(a - m);
        }
#pragma unroll
        for (int o = 16; o; o >>= 1) dp += __shfl_xor_sync(0xFFFFFFFFu, dp, o);
        float inv = 1.f / dp;

        // gather pass: full warp per edge
        float wself = expf(sa - m) * inv;
        float4 xv = ((const float4*)(g_x + (size_t)w * Dc))[l];
        float ax = xv.x * wself, ay = xv.y * wself, az = xv.z * wself, aw = xv.w * wself;
        for (int e = s0; e < s1; e++) {
            int s = __ldg(&g_csr[e]);
            float a = nir + g_nj[base + s];
            a = a >= 0.f ? a : 0.2f * a;
            float wt = expf(a - m) * inv;
            float4 v = ((const float4*)(g_x + (size_t)(base + s) * Dc))[l];
            ax += v.x * wt; ay += v.y * wt; az += v.z * wt; aw += v.w * wt;
        }
        float4 agg;
        agg.x = ax + bias.x; agg.y = ay + bias.y;
        agg.z = az + bias.z; agg.w = aw + bias.w;
        ((float4*)(g_agg + (size_t)w * Dc))[l] = agg;

        ls0 += agg.x; lq0 += agg.x * agg.x;
        ls1 += agg.y; lq1 += agg.y * agg.y;
        ls2 += agg.z; lq2 += agg.z * agg.z;
        ls3 += agg.w; lq3 += agg.w * agg.w;
    }

    atomicAdd(&ss[l * 4 + 0], ls0);  atomicAdd(&sq[l * 4 + 0], lq0);
    atomicAdd(&ss[l * 4 + 1], ls1);  atomicAdd(&sq[l * 4 + 1], lq1);
    atomicAdd(&ss[l * 4 + 2], ls2);  atomicAdd(&sq[l * 4 + 2], lq2);
    atomicAdd(&ss[l * 4 + 3], ls3);  atomicAdd(&sq[l * 4 + 3], lq3);
    __syncthreads();
    if (tid < 128) atomicAdd(&g_bnsum[tid], ss[tid]);
    else           atomicAdd(&g_bnsq[tid - 128], sq[tid - 128]);
}

__global__ void k_bnfin(const float* __restrict__ gamma, const float* __restrict__ beta) {
    int t = threadIdx.x;
    float mu = g_bnsum[t] / (float)BNc;
    float var = g_bnsq[t] / (float)BNc - mu * mu;
    float rstd = rsqrtf(var + 1e-5f);
    float sc = gamma[t] * rstd;
    g_scale[t] = sc;
    g_shift[t] = beta[t] - mu * sc;
}

// ---------------- GEMM 2 + epilogue: out = relu(s@W1a^T + u + b1e) . cvec ----
__global__ __launch_bounds__(256) void k_gemm2(const float* __restrict__ f_w1,
                                               float* __restrict__ out) {
    extern __shared__ float sm[];
    float* As = sm;             // [128][65]  s tile (BN+relu applied on load)
    float* Bs = sm + 128 * 65;  // [128][129] W1a transposed
    int tid = threadIdx.x;
    int row0 = blockIdx.x * 64;

    for (int idx = tid; idx < 64 * 128; idx += 256) {
        int m = idx >> 7, j = idx & 127;
        float v = g_agg[(size_t)(row0 + m) * Dc + j];
        float s = v * g_scale[j] + g_shift[j];
        As[j * 65 + m] = s > 0.f ? s : 0.f;
    }
    for (int idx = tid; idx < 128 * 128; idx += 256) {
        int ko = idx >> 7, j = idx & 127;
        Bs[j * 129 + ko] = f_w1[ko * 2 * Dc + j];
    }
    __syncthreads();

    int ty = tid >> 5, lane = tid & 31;
    int rb = ty * 8;
    float acc[8][4];
#pragma unroll
    for (int i = 0; i < 8; i++)
#pragma unroll
        for (int j = 0; j < 4; j++) acc[i][j] = 0.f;

    float cv[4], b1r[4];
#pragma unroll
    for (int jj = 0; jj < 4; jj++) {
        int col = lane + 32 * jj;
        cv[jj] = g_cvec[col];
        b1r[jj] = g_b1e[col];
    }

#pragma unroll 4
    for (int k = 0; k < 128; k++) {
        float a[8], bv[4];
#pragma unroll
        for (int i = 0; i < 8; i++) a[i] = As[k * 65 + rb + i];
#pragma unroll
        for (int jj = 0; jj < 4; jj++) bv[jj] = Bs[k * 129 + lane + 32 * jj];
#pragma unroll
        for (int i = 0; i < 8; i++)
#pragma unroll
            for (int jj = 0; jj < 4; jj++) acc[i][jj] += a[i] * bv[jj];
    }

    float b0 = g_b0;
#pragma unroll
    for (int i = 0; i < 8; i++) {
        int row = row0 + rb + i;
        float part = 0.f;
#pragma unroll
        for (int jj = 0; jj < 4; jj++) {
            int col = lane + 32 * jj;
            float h = acc[i][jj] + g_u[(size_t)row * Dc + col] + b1r[jj];
            h = h > 0.f ? h : 0.f;
            part += h * cv[jj];
        }
#pragma unroll
        for (int o = 16; o; o >>= 1) part += __shfl_xor_sync(0xFFFFFFFFu, part, o);
        if (!lane) out[row] = part + b0;
    }
}

// ---------------- launch ------------------------------------------------------
extern "C" void kernel_launch(void* const* d_in, const int* in_sizes, int n_in,
                              void* d_out, int out_size) {
    const float* data    = (const float*)d_in[0];
    const int*   ei      = (const int*)d_in[1];
    const float* emb     = (const float*)d_in[2];
    const float* lin_w   = (const float*)d_in[3];
    const float* att_i   = (const float*)d_in[4];
    const float* att_j   = (const float*)d_in[5];
    const float* aei     = (const float*)d_in[6];
    const float* aej     = (const float*)d_in[7];
    const float* gnn_b   = (const float*)d_in[8];
    const float* gamma   = (const float*)d_in[9];
    const float* beta    = (const float*)d_in[10];
    const float* v_w     = (const float*)d_in[15];
    const float* v_b     = (const float*)d_in[16];
    const float* f_w1    = (const float*)d_in[18];
    const float* f_b1    = (const float*)d_in[19];
    const float* f_w2    = (const float*)d_in[20];
    const float* f_b2    = (const float*)d_in[21];
    const float* out_w   = (const float*)d_in[22];
    const float* out_b   = (const float*)d_in[23];
    float* out = (float*)d_out;

    size_t sm1 = (size_t)(128 * 65 + 128 * 129) * 4;  // 99,328 B
    size_t sm2 = sm1;
    cudaFuncSetAttribute(k_gemm1, cudaFuncAttributeMaxDynamicSharedMemorySize, (int)sm1);
    cudaFuncSetAttribute(k_gemm2, cudaFuncAttributeMaxDynamicSharedMemorySize, (int)sm2);

    k_misc<<<1, 256>>>(f_w1, f_b1, f_w2, f_b2, v_b, out_w, out_b);
    k_w1b<<<128, 128>>>(f_w1, v_w);
    k_emb<<<125, 256>>>(emb, aei, aej);
    k_deg<<<40, 512>>>(ei);
    k_scan<<<1, 1024>>>();
    k_fill2<<<(Ec + 255) / 256, 256>>>(ei);
    k_gemm1<<<1000, 256, sm1>>>(data, lin_w, att_i, att_j);
    k_agg<<<1000, 256>>>(gnn_b);
    k_bnfin<<<1, 128>>>(gamma, beta);
    k_gemm2<<<1000, 256, sm2>>>(f_w1, out);
}

// round 4
// speedup vs baseline: 4.6198x; 1.6281x over previous
#include <cuda_runtime.h>
#include <math.h>
#include <stdint.h>

#define Bc   64
#define Nc   1000
#define Dc   128
#define Ec   20000
#define BNc  64000

#define PITA 132   // As pitch (floats): banks 4g+c -> conflict-free A frags
#define PITB 136   // Bs pitch (floats): banks 8c+g -> conflict-free B frags

// ---------------- scratch (static device globals; no allocation) -------------
__device__ float g_x[BNc * Dc];      // X @ lin_w^T
__device__ float g_u[BNc * Dc];      // X @ W1b_eff^T (folded temporal branch)
__device__ float g_agg[BNc * Dc];    // graph aggregation output
__device__ float g_ni[BNc];
__device__ float g_nj[BNc];
__device__ float g_esi[Nc];
__device__ float g_esj[Nc];
__device__ float g_linT[Dc * Dc];    // lin_w^T  (k-major [k][n])
__device__ float g_W1bT[Dc * Dc];    // (f_w1[:,128:] @ v_w)^T (k-major)
__device__ float g_fw1aT[Dc * Dc];   // f_w1[:, :128]^T (k-major [j][ko])
__device__ float g_b1e[Dc];
__device__ float g_cvec[Dc];         // f_w2^T @ out_w^T
__device__ float g_b0;
__device__ int   g_deg[Nc];
__device__ int   g_rowptr[Nc + 1];
__device__ int   g_cur[Nc];
__device__ int   g_csr[Ec];
__device__ float g_bnsum[Dc];
__device__ float g_bnsq[Dc];
__device__ float g_scale[Dc];
__device__ float g_shift[Dc];

__device__ __forceinline__ uint32_t to_tf32(float v) {
    uint32_t r;
    asm("cvt.rna.tf32.f32 %0, %1;" : "=r"(r) : "f"(v));
    return r;
}

__device__ __forceinline__ void mma_tf32(float* c, const uint32_t* a, const uint32_t* b) {
    asm volatile(
        "mma.sync.aligned.m16n8k8.row.col.f32.tf32.tf32.f32 "
        "{%0,%1,%2,%3}, {%4,%5,%6,%7}, {%8,%9}, {%0,%1,%2,%3};"
        : "+f"(c[0]), "+f"(c[1]), "+f"(c[2]), "+f"(c[3])
        : "r"(a[0]), "r"(a[1]), "r"(a[2]), "r"(a[3]), "r"(b[0]), "r"(b[1]));
}

// ---------------- tiny prep kernels ------------------------------------------
__global__ void k_misc(const float* __restrict__ f_w1, const float* __restrict__ f_b1,
                       const float* __restrict__ f_w2, const float* __restrict__ f_b2,
                       const float* __restrict__ v_b,  const float* __restrict__ out_w,
                       const float* __restrict__ out_b) {
    int t = threadIdx.x;
    if (t < Dc) {
        float acc = 0.f, cv = 0.f;
        for (int d = 0; d < Dc; d++) {
            acc += f_w1[t * 2 * Dc + Dc + d] * v_b[d];
            cv  += out_w[d] * f_w2[d * Dc + t];
        }
        g_b1e[t]  = f_b1[t] + acc;
        g_cvec[t] = cv;
        g_bnsum[t] = 0.f;
        g_bnsq[t]  = 0.f;
    }
    if (t == 0) {
        float b0 = out_b[0];
        for (int d = 0; d < Dc; d++) b0 += out_w[d] * f_b2[d];
        g_b0 = b0;
    }
    for (int i = t; i < Nc; i += blockDim.x) g_deg[i] = 0;
}

// W1b_eff^T[c][ko] = sum_d f_w1[ko][128+d] * v_w[d][c]
__global__ void k_w1b(const float* __restrict__ f_w1, const float* __restrict__ v_w) {
    int ko = blockIdx.x, c = threadIdx.x;
    const float* row = f_w1 + ko * 2 * Dc + Dc;
    float acc = 0.f;
#pragma unroll 8
    for (int d = 0; d < Dc; d++) acc += row[d] * v_w[d * Dc + c];
    g_W1bT[c * Dc + ko] = acc;
}

// transpose lin_w and f_w1[:, :128] into k-major
__global__ void k_tr(const float* __restrict__ lin_w, const float* __restrict__ f_w1) {
    int idx = blockIdx.x * 256 + threadIdx.x;
    if (idx >= Dc * Dc) return;
    int n = idx >> 7, k = idx & 127;
    g_linT[k * Dc + n] = lin_w[idx];            // lin_w[n][k]
    g_fw1aT[k * Dc + n] = f_w1[n * 2 * Dc + k]; // f_w1[n(ko)][k(j)]
}

// per-graph-node embedding scores (warp per row)
__global__ void k_emb(const float* __restrict__ emb, const float* __restrict__ aei,
                      const float* __restrict__ aej) {
    int w = blockIdx.x * 8 + (threadIdx.x >> 5);
    int l = threadIdx.x & 31;
    if (w >= Nc) return;
    float4 ev = ((const float4*)(emb + w * Dc))[l];
    float4 ai = ((const float4*)aei)[l];
    float4 aj = ((const float4*)aej)[l];
    float si = ev.x * ai.x + ev.y * ai.y + ev.z * ai.z + ev.w * ai.w;
    float sj = ev.x * aj.x + ev.y * aj.y + ev.z * aj.z + ev.w * aj.w;
#pragma unroll
    for (int o = 16; o; o >>= 1) {
        si += __shfl_xor_sync(0xFFFFFFFFu, si, o);
        sj += __shfl_xor_sync(0xFFFFFFFFu, sj, o);
    }
    if (!l) { g_esi[w] = si; g_esj[w] = sj; }
}

__global__ void k_deg(const int* __restrict__ ei) {
    int e = blockIdx.x * blockDim.x + threadIdx.x;
    if (e < Ec) atomicAdd(&g_deg[ei[Ec + e]], 1);
}

__global__ void k_scan() {
    __shared__ int sd[1024];
    int t = threadIdx.x;
    int d0 = (t < Nc) ? g_deg[t] : 0;
    sd[t] = d0;
    __syncthreads();
    for (int off = 1; off < 1024; off <<= 1) {
        int tmp = (t >= off) ? sd[t - off] : 0;
        __syncthreads();
        sd[t] += tmp;
        __syncthreads();
    }
    if (t == 0) g_rowptr[0] = 0;
    if (t < Nc) { g_rowptr[t + 1] = sd[t]; g_cur[t] = sd[t] - d0; }
}

__global__ void k_fill2(const int* __restrict__ ei) {
    int e = blockIdx.x * blockDim.x + threadIdx.x;
    if (e >= Ec) return;
    int d = ei[Ec + e];
    int p = atomicAdd(&g_cur[d], 1);
    g_csr[p] = ei[e];
}

// ---------------- GEMM 1 (tf32 mma): x = X@lin_w^T, u = X@W1b_eff^T ----------
// block: 64 rows x 128 cols, K=128. 8 warps as 2x4, each owns a 32x32 tile.
__global__ __launch_bounds__(256) void k_gemm1(const float* __restrict__ data) {
    extern __shared__ float sm[];
    float* As = sm;                 // [64][PITA]  m-major (tf32 bits)
    float* Bs = sm + 64 * PITA;     // [128][PITB] k-major (tf32 bits)
    const uint32_t* Asu = (const uint32_t*)As;
    const uint32_t* Bsu = (const uint32_t*)Bs;

    int tid = threadIdx.x;
    int warp = tid >> 5, lane = tid & 31;
    int wm = warp >> 2, wn = warp & 3;       // 2 x 4
    int g = lane >> 2, c = lane & 3;
    int row0 = blockIdx.x * 64;

    // load A tile (convert to tf32)
    for (int idx = tid; idx < 64 * 32; idx += 256) {
        int m = idx >> 5, k4 = idx & 31;
        float4 v = ((const float4*)(data + (size_t)(row0 + m) * Dc))[k4];
        uint4 u;
        u.x = to_tf32(v.x); u.y = to_tf32(v.y); u.z = to_tf32(v.z); u.w = to_tf32(v.w);
        *(uint4*)(As + m * PITA + k4 * 4) = u;
    }

    for (int cg = 0; cg < 2; cg++) {
        const float* Bsrc = cg ? g_W1bT : g_linT;   // k-major [k][n]
        __syncthreads();
        for (int idx = tid; idx < 128 * 32; idx += 256) {
            int k = idx >> 5, n4 = idx & 31;
            float4 v = ((const float4*)(Bsrc + (size_t)k * Dc))[n4];
            uint4 u;
            u.x = to_tf32(v.x); u.y = to_tf32(v.y); u.z = to_tf32(v.z); u.w = to_tf32(v.w);
            *(uint4*)(Bs + k * PITB + n4 * 4) = u;
        }
        __syncthreads();

        float acc[2][4][4];
#pragma unroll
        for (int mt = 0; mt < 2; mt++)
#pragma unroll
            for (int nt = 0; nt < 4; nt++)
#pragma unroll
                for (int r = 0; r < 4; r++) acc[mt][nt][r] = 0.f;

#pragma unroll 4
        for (int ks = 0; ks < 16; ks++) {
            int k0 = ks * 8;
            uint32_t a[2][4], b[4][2];
#pragma unroll
            for (int mt = 0; mt < 2; mt++) {
                int base = (wm * 32 + mt * 16 + g) * PITA + k0 + c;
                a[mt][0] = Asu[base];
                a[mt][1] = Asu[base + 8 * PITA];
                a[mt][2] = Asu[base + 4];
                a[mt][3] = Asu[base + 8 * PITA + 4];
            }
#pragma unroll
            for (int nt = 0; nt < 4; nt++) {
                int col = wn * 32 + nt * 8 + g;
                b[nt][0] = Bsu[(k0 + c) * PITB + col];
                b[nt][1] = Bsu[(k0 + 4 + c) * PITB + col];
            }
#pragma unroll
            for (int mt = 0; mt < 2; mt++)
#pragma unroll
                for (int nt = 0; nt < 4; nt++) mma_tf32(acc[mt][nt], a[mt], b[nt]);
        }

        float* dst = cg ? g_u : g_x;
#pragma unroll
        for (int mt = 0; mt < 2; mt++) {
            int row = row0 + wm * 32 + mt * 16 + g;
#pragma unroll
            for (int nt = 0; nt < 4; nt++) {
                int col = wn * 32 + nt * 8 + 2 * c;
                *(float2*)(dst + (size_t)row * Dc + col)       = make_float2(acc[mt][nt][0], acc[mt][nt][1]);
                *(float2*)(dst + (size_t)(row + 8) * Dc + col) = make_float2(acc[mt][nt][2], acc[mt][nt][3]);
            }
        }
    }
}

// ni/nj per row (warp per row)
__global__ void k_scores(const float* __restrict__ att_i, const float* __restrict__ att_j) {
    int w = blockIdx.x * 8 + (threadIdx.x >> 5);
    int l = threadIdx.x & 31;
    float4 xv = ((const float4*)(g_x + (size_t)w * Dc))[l];
    float4 ai = ((const float4*)att_i)[l];
    float4 aj = ((const float4*)att_j)[l];
    float si = xv.x * ai.x + xv.y * ai.y + xv.z * ai.z + xv.w * ai.w;
    float sj = xv.x * aj.x + xv.y * aj.y + xv.z * aj.z + xv.w * aj.w;
#pragma unroll
    for (int o = 16; o; o >>= 1) {
        si += __shfl_xor_sync(0xFFFFFFFFu, si, o);
        sj += __shfl_xor_sync(0xFFFFFFFFu, sj, o);
    }
    if (!l) {
        int n = w % Nc;
        g_ni[w] = si + g_esi[n];
        g_nj[w] = sj + g_esj[n];
    }
}

// ---------------- graph attention aggregation (single pass, no max-shift) ----
// alpha = O(0.3) so exp() is safe without max subtraction.
__global__ __launch_bounds__(256) void k_agg(const float* __restrict__ gnn_bias) {
    __shared__ float ss[128], sq[128];
    int tid = threadIdx.x;
    if (tid < 128) { ss[tid] = 0.f; sq[tid] = 0.f; }
    __syncthreads();

    int warp = tid >> 5, l = tid & 31;
    float4 bias = ((const float4*)gnn_bias)[l];
    float ls0 = 0.f, ls1 = 0.f, ls2 = 0.f, ls3 = 0.f;
    float lq0 = 0.f, lq1 = 0.f, lq2 = 0.f, lq3 = 0.f;

    for (int it = 0; it < 8; it++) {
        int w = blockIdx.x * 64 + it * 8 + warp;
        int b = w / Nc;
        int i = w - b * Nc;
        int base = b * Nc;

        float nir = g_ni[w];
        float sa = nir + g_nj[w];
        sa = sa >= 0.f ? sa : 0.2f * sa;
        float exs = __expf(sa);
        float den = exs;
        float4 xv = ((const float4*)(g_x + (size_t)w * Dc))[l];
        float ax = xv.x * exs, ay = xv.y * exs, az = xv.z * exs, aw = xv.w * exs;

        int s0 = g_rowptr[i], s1 = g_rowptr[i + 1];
        int s_next = (s0 < s1) ? __ldg(&g_csr[s0]) : 0;
        for (int e = s0; e < s1; e++) {
            int s = s_next;
            if (e + 1 < s1) s_next = __ldg(&g_csr[e + 1]);
            float a = nir + g_nj[base + s];
            a = a >= 0.f ? a : 0.2f * a;
            float ex = __expf(a);
            den += ex;
            float4 v = ((const float4*)(g_x + (size_t)(base + s) * Dc))[l];
            ax += v.x * ex; ay += v.y * ex; az += v.z * ex; aw += v.w * ex;
        }
        float inv = 1.f / den;
        float4 agg;
        agg.x = ax * inv + bias.x; agg.y = ay * inv + bias.y;
        agg.z = az * inv + bias.z; agg.w = aw * inv + bias.w;
        ((float4*)(g_agg + (size_t)w * Dc))[l] = agg;

        ls0 += agg.x; lq0 += agg.x * agg.x;
        ls1 += agg.y; lq1 += agg.y * agg.y;
        ls2 += agg.z; lq2 += agg.z * agg.z;
        ls3 += agg.w; lq3 += agg.w * agg.w;
    }

    atomicAdd(&ss[l * 4 + 0], ls0);  atomicAdd(&sq[l * 4 + 0], lq0);
    atomicAdd(&ss[l * 4 + 1], ls1);  atomicAdd(&sq[l * 4 + 1], lq1);
    atomicAdd(&ss[l * 4 + 2], ls2);  atomicAdd(&sq[l * 4 + 2], lq2);
    atomicAdd(&ss[l * 4 + 3], ls3);  atomicAdd(&sq[l * 4 + 3], lq3);
    __syncthreads();
    if (tid < 128) atomicAdd(&g_bnsum[tid], ss[tid]);
    else           atomicAdd(&g_bnsq[tid - 128], sq[tid - 128]);
}

__global__ void k_bnfin(const float* __restrict__ gamma, const float* __restrict__ beta) {
    int t = threadIdx.x;
    float mu = g_bnsum[t] / (float)BNc;
    float var = g_bnsq[t] / (float)BNc - mu * mu;
    float rstd = rsqrtf(var + 1e-5f);
    float sc = gamma[t] * rstd;
    g_scale[t] = sc;
    g_shift[t] = beta[t] - mu * sc;
}

// ---------------- GEMM 2 (tf32 mma) + epilogue -------------------------------
// out = relu( relu(BN(agg)) @ W1a^T + u + b1e ) . cvec + b0
__global__ __launch_bounds__(256) void k_gemm2(float* __restrict__ out) {
    extern __shared__ float sm[];
    float* As = sm;                 // [64][PITA]  s tile (BN+relu, tf32 bits)
    float* Bs = sm + 64 * PITA;     // [128][PITB] W1a^T k-major (tf32 bits)
    float* spart = Bs;              // reuse after mma for row partials
    const uint32_t* Asu = (const uint32_t*)As;
    const uint32_t* Bsu = (const uint32_t*)Bs;

    int tid = threadIdx.x;
    int warp = tid >> 5, lane = tid & 31;
    int wm = warp >> 2, wn = warp & 3;
    int g = lane >> 2, c = lane & 3;
    int row0 = blockIdx.x * 64;

    uint32_t* Asw = (uint32_t*)As;
    for (int idx = tid; idx < 64 * 128; idx += 256) {
        int m = idx >> 7, j = idx & 127;
        float v = g_agg[(size_t)(row0 + m) * Dc + j];
        float s = v * g_scale[j] + g_shift[j];
        Asw[m * PITA + j] = to_tf32(s > 0.f ? s : 0.f);
    }
    for (int idx = tid; idx < 128 * 32; idx += 256) {
        int k = idx >> 5, n4 = idx & 31;
        float4 v = ((const float4*)(g_fw1aT + (size_t)k * Dc))[n4];
        uint4 u;
        u.x = to_tf32(v.x); u.y = to_tf32(v.y); u.z = to_tf32(v.z); u.w = to_tf32(v.w);
        *(uint4*)(Bs + k * PITB + n4 * 4) = u;
    }
    __syncthreads();

    float acc[2][4][4];
#pragma unroll
    for (int mt = 0; mt < 2; mt++)
#pragma unroll
        for (int nt = 0; nt < 4; nt++)
#pragma unroll
            for (int r = 0; r < 4; r++) acc[mt][nt][r] = 0.f;

#pragma unroll 4
    for (int ks = 0; ks < 16; ks++) {
        int k0 = ks * 8;
        uint32_t a[2][4], b[4][2];
#pragma unroll
        for (int mt = 0; mt < 2; mt++) {
            int base = (wm * 32 + mt * 16 + g) * PITA + k0 + c;
            a[mt][0] = Asu[base];
            a[mt][1] = Asu[base + 8 * PITA];
            a[mt][2] = Asu[base + 4];
            a[mt][3] = Asu[base + 8 * PITA + 4];
        }
#pragma unroll
        for (int nt = 0; nt < 4; nt++) {
            int col = wn * 32 + nt * 8 + g;
            b[nt][0] = Bsu[(k0 + c) * PITB + col];
            b[nt][1] = Bsu[(k0 + 4 + c) * PITB + col];
        }
#pragma unroll
        for (int mt = 0; mt < 2; mt++)
#pragma unroll
            for (int nt = 0; nt < 4; nt++) mma_tf32(acc[mt][nt], a[mt], b[nt]);
    }
    __syncthreads();
    if (tid < 64) spart[tid] = 0.f;
    __syncthreads();

    // epilogue: h = relu(acc + u + b1e); partial = sum h*cvec over this thread's cols
    float cv[4][2], b1[4][2];
#pragma unroll
    for (int nt = 0; nt < 4; nt++) {
        int col = wn * 32 + nt * 8 + 2 * c;
        cv[nt][0] = g_cvec[col];     cv[nt][1] = g_cvec[col + 1];
        b1[nt][0] = g_b1e[col];      b1[nt][1] = g_b1e[col + 1];
    }
#pragma unroll
    for (int mt = 0; mt < 2; mt++) {
        int rloc = wm * 32 + mt * 16 + g;
#pragma unroll
        for (int half = 0; half < 2; half++) {
            int row = rloc + half * 8;
            float part = 0.f;
#pragma unroll
            for (int nt = 0; nt < 4; nt++) {
                int col = wn * 32 + nt * 8 + 2 * c;
                float2 uv = *(const float2*)(g_u + (size_t)(row0 + row) * Dc + col);
                float h0 = acc[mt][nt][half * 2 + 0] + uv.x + b1[nt][0];
                float h1 = acc[mt][nt][half * 2 + 1] + uv.y + b1[nt][1];
                h0 = h0 > 0.f ? h0 : 0.f;
                h1 = h1 > 0.f ? h1 : 0.f;
                part += h0 * cv[nt][0] + h1 * cv[nt][1];
            }
            atomicAdd(&spart[row], part);
        }
    }
    __syncthreads();
    if (tid < 64) out[row0 + tid] = spart[tid] + g_b0;
}

// ---------------- launch ------------------------------------------------------
extern "C" void kernel_launch(void* const* d_in, const int* in_sizes, int n_in,
                              void* d_out, int out_size) {
    const float* data    = (const float*)d_in[0];
    const int*   ei      = (const int*)d_in[1];
    const float* emb     = (const float*)d_in[2];
    const float* lin_w   = (const float*)d_in[3];
    const float* att_i   = (const float*)d_in[4];
    const float* att_j   = (const float*)d_in[5];
    const float* aei     = (const float*)d_in[6];
    const float* aej     = (const float*)d_in[7];
    const float* gnn_b   = (const float*)d_in[8];
    const float* gamma   = (const float*)d_in[9];
    const float* beta    = (const float*)d_in[10];
    const float* v_w     = (const float*)d_in[15];
    const float* v_b     = (const float*)d_in[16];
    const float* f_w1    = (const float*)d_in[18];
    const float* f_b1    = (const float*)d_in[19];
    const float* f_w2    = (const float*)d_in[20];
    const float* f_b2    = (const float*)d_in[21];
    const float* out_w   = (const float*)d_in[22];
    const float* out_b   = (const float*)d_in[23];
    float* out = (float*)d_out;

    size_t smg = (size_t)(64 * PITA + 128 * PITB) * 4;   // 103,424 B
    cudaFuncSetAttribute(k_gemm1, cudaFuncAttributeMaxDynamicSharedMemorySize, (int)smg);
    cudaFuncSetAttribute(k_gemm2, cudaFuncAttributeMaxDynamicSharedMemorySize, (int)smg);

    k_misc<<<1, 256>>>(f_w1, f_b1, f_w2, f_b2, v_b, out_w, out_b);
    k_w1b<<<128, 128>>>(f_w1, v_w);
    k_tr<<<64, 256>>>(lin_w, f_w1);
    k_emb<<<125, 256>>>(emb, aei, aej);
    k_deg<<<40, 512>>>(ei);
    k_scan<<<1, 1024>>>();
    k_fill2<<<(Ec + 255) / 256, 256>>>(ei);
    k_gemm1<<<1000, 256, smg>>>(data);
    k_scores<<<8000, 256>>>(att_i, att_j);
    k_agg<<<1000, 256>>>(gnn_b);
    k_bnfin<<<1, 128>>>(gamma, beta);
    k_gemm2<<<1000, 256, smg>>>(out);
}

// round 5
// speedup vs baseline: 4.7733x; 1.0332x over previous
#include <cuda_runtime.h>
#include <math.h>
#include <stdint.h>

#define Bc   64
#define Nc   1000
#define Dc   128
#define Ec   20000
#define BNc  64000

#define PITA 132   // As pitch (floats): conflict-free A frags
#define PITB 136   // Bs pitch (floats): conflict-free B frags

// ---------------- scratch (static device globals; no allocation) -------------
__device__ float g_x[BNc * Dc];      // X @ lin_w^T
__device__ float g_u[BNc * Dc];      // X @ W1b_eff^T (folded temporal branch)
__device__ float g_agg[BNc * Dc];    // graph aggregation output
__device__ float g_ni[BNc];
__device__ float g_nj[BNc];
__device__ float g_esi[Nc];
__device__ float g_esj[Nc];
__device__ float g_linT[Dc * Dc];    // lin_w^T  (k-major [k][n])
__device__ float g_W1bT[Dc * Dc];    // (f_w1[:,128:] @ v_w)^T (k-major)
__device__ float g_fw1aT[Dc * Dc];   // f_w1[:, :128]^T (k-major [j][ko])
__device__ float g_b1e[Dc];
__device__ float g_cvec[Dc];         // f_w2^T @ out_w^T
__device__ float g_b0;
__device__ int   g_rowptr[Nc + 1];
__device__ int   g_cur[Nc];
__device__ int   g_csr[Ec];
__device__ float g_bnsum[Dc];
__device__ float g_bnsq[Dc];

__device__ __forceinline__ uint32_t to_tf32(float v) {
    uint32_t r;
    asm("cvt.rna.tf32.f32 %0, %1;" : "=r"(r) : "f"(v));
    return r;
}

__device__ __forceinline__ void mma_tf32(float* c, const uint32_t* a, const uint32_t* b) {
    asm volatile(
        "mma.sync.aligned.m16n8k8.row.col.f32.tf32.tf32.f32 "
        "{%0,%1,%2,%3}, {%4,%5,%6,%7}, {%8,%9}, {%0,%1,%2,%3};"
        : "+f"(c[0]), "+f"(c[1]), "+f"(c[2]), "+f"(c[3])
        : "r"(a[0]), "r"(a[1]), "r"(a[2]), "r"(a[3]), "r"(b[0]), "r"(b[1]));
}

// ---------------- fused prep: w1b + transposes + emb scores + misc -----------
// grid = 254 blocks x 256 threads:
//   blocks 0..127   : W1bT column (t<128) + linT/fw1aT transpose rows (t>=128)
//   blocks 128..252 : emb scores, warp per row
//   block 253       : b1e, cvec, b0, bn zero
__global__ __launch_bounds__(256) void k_prep(
        const float* __restrict__ f_w1, const float* __restrict__ f_b1,
        const float* __restrict__ f_w2, const float* __restrict__ f_b2,
        const float* __restrict__ v_b,  const float* __restrict__ v_w,
        const float* __restrict__ out_w, const float* __restrict__ out_b,
        const float* __restrict__ lin_w,
        const float* __restrict__ emb, const float* __restrict__ aei,
        const float* __restrict__ aej) {
    int bi = blockIdx.x;
    int t = threadIdx.x;
    if (bi < 128) {
        if (t < 128) {
            // W1bT[c=t][ko=bi]
            const float* row = f_w1 + bi * 2 * Dc + Dc;
            float acc = 0.f;
#pragma unroll 8
            for (int d = 0; d < Dc; d++) acc += row[d] * v_w[d * Dc + t];
            g_W1bT[t * Dc + bi] = acc;
        } else {
            int k = t - 128;
            g_linT[k * Dc + bi]  = lin_w[bi * Dc + k];
            g_fw1aT[k * Dc + bi] = f_w1[bi * 2 * Dc + k];
        }
    } else if (bi < 253) {
        int w = (bi - 128) * 8 + (t >> 5);
        int l = t & 31;
        if (w < Nc) {
            float4 ev = ((const float4*)(emb + w * Dc))[l];
            float4 ai = ((const float4*)aei)[l];
            float4 aj = ((const float4*)aej)[l];
            float si = ev.x * ai.x + ev.y * ai.y + ev.z * ai.z + ev.w * ai.w;
            float sj = ev.x * aj.x + ev.y * aj.y + ev.z * aj.z + ev.w * aj.w;
#pragma unroll
            for (int o = 16; o; o >>= 1) {
                si += __shfl_xor_sync(0xFFFFFFFFu, si, o);
                sj += __shfl_xor_sync(0xFFFFFFFFu, sj, o);
            }
            if (!l) { g_esi[w] = si; g_esj[w] = sj; }
        }
    } else {
        if (t < Dc) {
            float acc = 0.f, cv = 0.f;
            for (int d = 0; d < Dc; d++) {
                acc += f_w1[t * 2 * Dc + Dc + d] * v_b[d];
                cv  += out_w[d] * f_w2[d * Dc + t];
            }
            g_b1e[t]  = f_b1[t] + acc;
            g_cvec[t] = cv;
            g_bnsum[t] = 0.f;
            g_bnsq[t]  = 0.f;
        }
        if (t == 0) {
            float b0 = out_b[0];
            for (int d = 0; d < Dc; d++) b0 += out_w[d] * f_b2[d];
            g_b0 = b0;
        }
    }
}

// ---------------- degree histogram + prefix scan (one block) -----------------
__global__ __launch_bounds__(1024) void k_scan(const int* __restrict__ ei) {
    __shared__ int sdeg[Nc];
    __shared__ int sd[1024];
    int t = threadIdx.x;
    for (int i = t; i < Nc; i += 1024) sdeg[i] = 0;
    __syncthreads();
    for (int e = t; e < Ec; e += 1024) atomicAdd(&sdeg[ei[Ec + e]], 1);
    __syncthreads();
    int d0 = (t < Nc) ? sdeg[t] : 0;
    sd[t] = d0;
    __syncthreads();
    for (int off = 1; off < 1024; off <<= 1) {
        int tmp = (t >= off) ? sd[t - off] : 0;
        __syncthreads();
        sd[t] += tmp;
        __syncthreads();
    }
    if (t == 0) g_rowptr[0] = 0;
    if (t < Nc) { g_rowptr[t + 1] = sd[t]; g_cur[t] = sd[t] - d0; }
}

__global__ void k_fill2(const int* __restrict__ ei) {
    int e = blockIdx.x * blockDim.x + threadIdx.x;
    if (e >= Ec) return;
    int d = ei[Ec + e];
    int p = atomicAdd(&g_cur[d], 1);
    g_csr[p] = ei[e];
}

// ---------------- GEMM 1 (tf32 mma) + fused attention scores -----------------
// x = X@lin_w^T, u = X@W1b_eff^T; ni/nj computed from x accumulators.
__global__ __launch_bounds__(256) void k_gemm1(const float* __restrict__ data,
                                               const float* __restrict__ att_i,
                                               const float* __restrict__ att_j) {
    extern __shared__ float sm[];
    float* As = sm;                 // [64][PITA]  m-major (tf32 bits)
    float* Bs = sm + 64 * PITA;     // [128][PITB] k-major (tf32 bits)
    __shared__ float s_si[64], s_sj[64];
    const uint32_t* Asu = (const uint32_t*)As;
    const uint32_t* Bsu = (const uint32_t*)Bs;

    int tid = threadIdx.x;
    int warp = tid >> 5, lane = tid & 31;
    int wm = warp >> 2, wn = warp & 3;       // 2 x 4
    int g = lane >> 2, c = lane & 3;
    int row0 = blockIdx.x * 64;

    if (tid < 64) { s_si[tid] = 0.f; s_sj[tid] = 0.f; }

    // load A tile (convert to tf32)
    for (int idx = tid; idx < 64 * 32; idx += 256) {
        int m = idx >> 5, k4 = idx & 31;
        float4 v = ((const float4*)(data + (size_t)(row0 + m) * Dc))[k4];
        uint4 u;
        u.x = to_tf32(v.x); u.y = to_tf32(v.y); u.z = to_tf32(v.z); u.w = to_tf32(v.w);
        *(uint4*)(As + m * PITA + k4 * 4) = u;
    }

    for (int cg = 0; cg < 2; cg++) {
        const float* Bsrc = cg ? g_W1bT : g_linT;   // k-major [k][n]
        __syncthreads();
        for (int idx = tid; idx < 128 * 32; idx += 256) {
            int k = idx >> 5, n4 = idx & 31;
            float4 v = ((const float4*)(Bsrc + (size_t)k * Dc))[n4];
            uint4 u;
            u.x = to_tf32(v.x); u.y = to_tf32(v.y); u.z = to_tf32(v.z); u.w = to_tf32(v.w);
            *(uint4*)(Bs + k * PITB + n4 * 4) = u;
        }
        __syncthreads();

        float acc[2][4][4];
#pragma unroll
        for (int mt = 0; mt < 2; mt++)
#pragma unroll
            for (int nt = 0; nt < 4; nt++)
#pragma unroll
                for (int r = 0; r < 4; r++) acc[mt][nt][r] = 0.f;

#pragma unroll 4
        for (int ks = 0; ks < 16; ks++) {
            int k0 = ks * 8;
            uint32_t a[2][4], b[4][2];
#pragma unroll
            for (int mt = 0; mt < 2; mt++) {
                int base = (wm * 32 + mt * 16 + g) * PITA + k0 + c;
                a[mt][0] = Asu[base];
                a[mt][1] = Asu[base + 8 * PITA];
                a[mt][2] = Asu[base + 4];
                a[mt][3] = Asu[base + 8 * PITA + 4];
            }
#pragma unroll
            for (int nt = 0; nt < 4; nt++) {
                int col = wn * 32 + nt * 8 + g;
                b[nt][0] = Bsu[(k0 + c) * PITB + col];
                b[nt][1] = Bsu[(k0 + 4 + c) * PITB + col];
            }
#pragma unroll
            for (int mt = 0; mt < 2; mt++)
#pragma unroll
                for (int nt = 0; nt < 4; nt++) mma_tf32(acc[mt][nt], a[mt], b[nt]);
        }

        float* dst = cg ? g_u : g_x;
#pragma unroll
        for (int mt = 0; mt < 2; mt++) {
            int row = row0 + wm * 32 + mt * 16 + g;
#pragma unroll
            for (int nt = 0; nt < 4; nt++) {
                int col = wn * 32 + nt * 8 + 2 * c;
                *(float2*)(dst + (size_t)row * Dc + col)       = make_float2(acc[mt][nt][0], acc[mt][nt][1]);
                *(float2*)(dst + (size_t)(row + 8) * Dc + col) = make_float2(acc[mt][nt][2], acc[mt][nt][3]);
            }
        }

        if (!cg) {
            // fused scores: partial dot of x rows with att_i / att_j
            float ai[4][2], aj[4][2];
#pragma unroll
            for (int nt = 0; nt < 4; nt++) {
                int col = wn * 32 + nt * 8 + 2 * c;
                ai[nt][0] = __ldg(&att_i[col]);     ai[nt][1] = __ldg(&att_i[col + 1]);
                aj[nt][0] = __ldg(&att_j[col]);     aj[nt][1] = __ldg(&att_j[col + 1]);
            }
#pragma unroll
            for (int mt = 0; mt < 2; mt++)
#pragma unroll
                for (int half = 0; half < 2; half++) {
                    int rloc = wm * 32 + mt * 16 + g + half * 8;
                    float si = 0.f, sj = 0.f;
#pragma unroll
                    for (int nt = 0; nt < 4; nt++) {
                        float v0 = acc[mt][nt][half * 2 + 0];
                        float v1 = acc[mt][nt][half * 2 + 1];
                        si += v0 * ai[nt][0] + v1 * ai[nt][1];
                        sj += v0 * aj[nt][0] + v1 * aj[nt][1];
                    }
                    // reduce over c lanes (lane bits 0..1)
                    si += __shfl_xor_sync(0xFFFFFFFFu, si, 1);
                    si += __shfl_xor_sync(0xFFFFFFFFu, si, 2);
                    sj += __shfl_xor_sync(0xFFFFFFFFu, sj, 1);
                    sj += __shfl_xor_sync(0xFFFFFFFFu, sj, 2);
                    if (c == 0) {
                        atomicAdd(&s_si[rloc], si);
                        atomicAdd(&s_sj[rloc], sj);
                    }
                }
        }
    }
    __syncthreads();
    if (tid < 64) {
        int row = row0 + tid;
        int n = row % Nc;
        g_ni[row] = s_si[tid] + g_esi[n];
        g_nj[row] = s_sj[tid] + g_esj[n];
    }
}

// ---------------- graph attention aggregation (single pass, no max-shift) ----
__global__ __launch_bounds__(256) void k_agg(const float* __restrict__ gnn_bias) {
    __shared__ float ss[128], sq[128];
    int tid = threadIdx.x;
    if (tid < 128) { ss[tid] = 0.f; sq[tid] = 0.f; }
    __syncthreads();

    int warp = tid >> 5, l = tid & 31;
    float4 bias = ((const float4*)gnn_bias)[l];
    float ls0 = 0.f, ls1 = 0.f, ls2 = 0.f, ls3 = 0.f;
    float lq0 = 0.f, lq1 = 0.f, lq2 = 0.f, lq3 = 0.f;

    for (int it = 0; it < 8; it++) {
        int w = blockIdx.x * 64 + it * 8 + warp;
        int b = w / Nc;
        int i = w - b * Nc;
        int base = b * Nc;

        float nir = g_ni[w];
        float sa = nir + g_nj[w];
        sa = sa >= 0.f ? sa : 0.2f * sa;
        float exs = __expf(sa);
        float den = exs;
        float4 xv = ((const float4*)(g_x + (size_t)w * Dc))[l];
        float ax = xv.x * exs, ay = xv.y * exs, az = xv.z * exs, aw = xv.w * exs;

        int s0 = g_rowptr[i], s1 = g_rowptr[i + 1];
        int s_next = (s0 < s1) ? __ldg(&g_csr[s0]) : 0;
        for (int e = s0; e < s1; e++) {
            int s = s_next;
            if (e + 1 < s1) s_next = __ldg(&g_csr[e + 1]);
            float a = nir + g_nj[base + s];
            a = a >= 0.f ? a : 0.2f * a;
            float ex = __expf(a);
            den += ex;
            float4 v = ((const float4*)(g_x + (size_t)(base + s) * Dc))[l];
            ax += v.x * ex; ay += v.y * ex; az += v.z * ex; aw += v.w * ex;
        }
        float inv = 1.f / den;
        float4 agg;
        agg.x = ax * inv + bias.x; agg.y = ay * inv + bias.y;
        agg.z = az * inv + bias.z; agg.w = aw * inv + bias.w;
        ((float4*)(g_agg + (size_t)w * Dc))[l] = agg;

        ls0 += agg.x; lq0 += agg.x * agg.x;
        ls1 += agg.y; lq1 += agg.y * agg.y;
        ls2 += agg.z; lq2 += agg.z * agg.z;
        ls3 += agg.w; lq3 += agg.w * agg.w;
    }

    atomicAdd(&ss[l * 4 + 0], ls0);  atomicAdd(&sq[l * 4 + 0], lq0);
    atomicAdd(&ss[l * 4 + 1], ls1);  atomicAdd(&sq[l * 4 + 1], lq1);
    atomicAdd(&ss[l * 4 + 2], ls2);  atomicAdd(&sq[l * 4 + 2], lq2);
    atomicAdd(&ss[l * 4 + 3], ls3);  atomicAdd(&sq[l * 4 + 3], lq3);
    __syncthreads();
    if (tid < 128) atomicAdd(&g_bnsum[tid], ss[tid]);
    else           atomicAdd(&g_bnsq[tid - 128], sq[tid - 128]);
}

// ---------------- GEMM 2 (tf32 mma) + BN finalize + epilogue -----------------
__global__ __launch_bounds__(256) void k_gemm2(const float* __restrict__ gamma,
                                               const float* __restrict__ beta,
                                               float* __restrict__ out) {
    extern __shared__ float sm[];
    float* As = sm;                 // [64][PITA]
    float* Bs = sm + 64 * PITA;     // [128][PITB]
    float* spart = Bs;              // reuse after mma for row partials
    __shared__ float s_scale[128], s_shift[128];
    const uint32_t* Asu = (const uint32_t*)As;
    const uint32_t* Bsu = (const uint32_t*)Bs;

    int tid = threadIdx.x;
    int warp = tid >> 5, lane = tid & 31;
    int wm = warp >> 2, wn = warp & 3;
    int g = lane >> 2, c = lane & 3;
    int row0 = blockIdx.x * 64;

    if (tid < 128) {
        float mu = g_bnsum[tid] / (float)BNc;
        float var = g_bnsq[tid] / (float)BNc - mu * mu;
        float rstd = rsqrtf(var + 1e-5f);
        float sc = gamma[tid] * rstd;
        s_scale[tid] = sc;
        s_shift[tid] = beta[tid] - mu * sc;
    }
    __syncthreads();

    uint32_t* Asw = (uint32_t*)As;
    for (int idx = tid; idx < 64 * 128; idx += 256) {
        int m = idx >> 7, j = idx & 127;
        float v = g_agg[(size_t)(row0 + m) * Dc + j];
        float s = v * s_scale[j] + s_shift[j];
        Asw[m * PITA + j] = to_tf32(s > 0.f ? s : 0.f);
    }
    for (int idx = tid; idx < 128 * 32; idx += 256) {
        int k = idx >> 5, n4 = idx & 31;
        float4 v = ((const float4*)(g_fw1aT + (size_t)k * Dc))[n4];
        uint4 u;
        u.x = to_tf32(v.x); u.y = to_tf32(v.y); u.z = to_tf32(v.z); u.w = to_tf32(v.w);
        *(uint4*)(Bs + k * PITB + n4 * 4) = u;
    }
    __syncthreads();

    float acc[2][4][4];
#pragma unroll
    for (int mt = 0; mt < 2; mt++)
#pragma unroll
        for (int nt = 0; nt < 4; nt++)
#pragma unroll
            for (int r = 0; r < 4; r++) acc[mt][nt][r] = 0.f;

#pragma unroll 4
    for (int ks = 0; ks < 16; ks++) {
        int k0 = ks * 8;
        uint32_t a[2][4], b[4][2];
#pragma unroll
        for (int mt = 0; mt < 2; mt++) {
            int base = (wm * 32 + mt * 16 + g) * PITA + k0 + c;
            a[mt][0] = Asu[base];
            a[mt][1] = Asu[base + 8 * PITA];
            a[mt][2] = Asu[base + 4];
            a[mt][3] = Asu[base + 8 * PITA + 4];
        }
#pragma unroll
        for (int nt = 0; nt < 4; nt++) {
            int col = wn * 32 + nt * 8 + g;
            b[nt][0] = Bsu[(k0 + c) * PITB + col];
            b[nt][1] = Bsu[(k0 + 4 + c) * PITB + col];
        }
#pragma unroll
        for (int mt = 0; mt < 2; mt++)
#pragma unroll
            for (int nt = 0; nt < 4; nt++) mma_tf32(acc[mt][nt], a[mt], b[nt]);
    }
    __syncthreads();
    if (tid < 64) spart[tid] = 0.f;
    __syncthreads();

    float cv[4][2], b1[4][2];
#pragma unroll
    for (int nt = 0; nt < 4; nt++) {
        int col = wn * 32 + nt * 8 + 2 * c;
        cv[nt][0] = g_cvec[col];     cv[nt][1] = g_cvec[col + 1];
        b1[nt][0] = g_b1e[col];      b1[nt][1] = g_b1e[col + 1];
    }
#pragma unroll
    for (int mt = 0; mt < 2; mt++) {
        int rloc = wm * 32 + mt * 16 + g;
#pragma unroll
        for (int half = 0; half < 2; half++) {
            int row = rloc + half * 8;
            float part = 0.f;
#pragma unroll
            for (int nt = 0; nt < 4; nt++) {
                int col = wn * 32 + nt * 8 + 2 * c;
                float2 uv = *(const float2*)(g_u + (size_t)(row0 + row) * Dc + col);
                float h0 = acc[mt][nt][half * 2 + 0] + uv.x + b1[nt][0];
                float h1 = acc[mt][nt][half * 2 + 1] + uv.y + b1[nt][1];
                h0 = h0 > 0.f ? h0 : 0.f;
                h1 = h1 > 0.f ? h1 : 0.f;
                part += h0 * cv[nt][0] + h1 * cv[nt][1];
            }
            atomicAdd(&spart[row], part);
        }
    }
    __syncthreads();
    if (tid < 64) out[row0 + tid] = spart[tid] + g_b0;
}

// ---------------- launch ------------------------------------------------------
extern "C" void kernel_launch(void* const* d_in, const int* in_sizes, int n_in,
                              void* d_out, int out_size) {
    const float* data    = (const float*)d_in[0];
    const int*   ei      = (const int*)d_in[1];
    const float* emb     = (const float*)d_in[2];
    const float* lin_w   = (const float*)d_in[3];
    const float* att_i   = (const float*)d_in[4];
    const float* att_j   = (const float*)d_in[5];
    const float* aei     = (const float*)d_in[6];
    const float* aej     = (const float*)d_in[7];
    const float* gnn_b   = (const float*)d_in[8];
    const float* gamma   = (const float*)d_in[9];
    const float* beta    = (const float*)d_in[10];
    const float* v_w     = (const float*)d_in[15];
    const float* v_b     = (const float*)d_in[16];
    const float* f_w1    = (const float*)d_in[18];
    const float* f_b1    = (const float*)d_in[19];
    const float* f_w2    = (const float*)d_in[20];
    const float* f_b2    = (const float*)d_in[21];
    const float* out_w   = (const float*)d_in[22];
    const float* out_b   = (const float*)d_in[23];
    float* out = (float*)d_out;

    size_t smg = (size_t)(64 * PITA + 128 * PITB) * 4;   // 103,424 B
    cudaFuncSetAttribute(k_gemm1, cudaFuncAttributeMaxDynamicSharedMemorySize, (int)smg);
    cudaFuncSetAttribute(k_gemm2, cudaFuncAttributeMaxDynamicSharedMemorySize, (int)smg);

    k_prep<<<254, 256>>>(f_w1, f_b1, f_w2, f_b2, v_b, v_w, out_w, out_b,
                         lin_w, emb, aei, aej);
    k_scan<<<1, 1024>>>(ei);
    k_fill2<<<(Ec + 255) / 256, 256>>>(ei);
    k_gemm1<<<1000, 256, smg>>>(data, att_i, att_j);
    k_agg<<<1000, 256>>>(gnn_b);
    k_gemm2<<<1000, 256, smg>>>(gamma, beta, out);
}